// round 13
// baseline (speedup 1.0000x reference)
#include <cuda_runtime.h>

// Problem constants
#define N_ROWS  65536      // B*A rows
#define NGROUPS 8192       // batches (groups of 8 agents)
#define PAD     68         // padded row width for smem (breaks bank conflicts, keeps 16B align)

// Scratch: Y[n][0:64] = query(n), Y[n][64:128] = Hh(n) (+wv1_b folded in)
__device__ float g_Y[N_ROWS * 128];

// ---------------------------------------------------------------------------
// Kernel 1: two fused SGEMMs (M=65536, N=64, K=256)
//   by==0: query = [o|o_next] @ wq_w^T + wq_b
//   by==1: Hh    = h @ wv1_w[:, :256]^T + wv1_b
// Tile: 64 rows x 64 cols, BK=32, 128 threads, 4x8 register tile per thread.
// ---------------------------------------------------------------------------
__global__ __launch_bounds__(128) void k1_gemm(
    const float* __restrict__ o, const float* __restrict__ o_next,
    const float* __restrict__ h,
    const float* __restrict__ wq_w, const float* __restrict__ wq_b,
    const float* __restrict__ wv1_w, const float* __restrict__ wv1_b)
{
    __shared__ float As[32][PAD];   // k-major: As[k][row]
    __shared__ float Ws[32][PAD];   // k-major: Ws[k][col]
    const int by   = blockIdx.y;
    const int row0 = blockIdx.x * 64;
    const int tid  = threadIdx.x;
    const int tx   = tid & 7;       // col group (8 cols)
    const int ty   = tid >> 3;      // row group (4 rows)
    const float* Wsrc   = (by == 0) ? wq_w : wv1_w;
    const int    wstrid = (by == 0) ? 256  : 288;

    float acc[4][8];
#pragma unroll
    for (int r = 0; r < 4; r++)
#pragma unroll
        for (int c = 0; c < 8; c++) acc[r][c] = 0.f;

    for (int kt = 0; kt < 8; kt++) {
        const int k0 = kt * 32;
        // Load A tile (64 rows x 32 k), transposed into k-major smem
#pragma unroll
        for (int i = 0; i < 4; i++) {
            int flat = tid + i * 128;          // 0..511 float4 slots
            int r    = flat >> 3;              // 0..63
            int k4   = (flat & 7) << 2;        // 0..28
            int kg   = k0 + k4;
            float4 v;
            if (by == 0) {
                if (kg < 128) v = *(const float4*)(o      + (row0 + r) * 128 + kg);
                else          v = *(const float4*)(o_next + (row0 + r) * 128 + (kg - 128));
            } else {
                v = *(const float4*)(h + (row0 + r) * 256 + kg);
            }
            As[k4 + 0][r] = v.x; As[k4 + 1][r] = v.y;
            As[k4 + 2][r] = v.z; As[k4 + 3][r] = v.w;
        }
        // Load W tile (64 cols x 32 k), transposed into k-major smem
#pragma unroll
        for (int i = 0; i < 4; i++) {
            int flat = tid + i * 128;
            int c    = flat >> 3;
            int k4   = (flat & 7) << 2;
            float4 v = *(const float4*)(Wsrc + c * wstrid + k0 + k4);
            Ws[k4 + 0][c] = v.x; Ws[k4 + 1][c] = v.y;
            Ws[k4 + 2][c] = v.z; Ws[k4 + 3][c] = v.w;
        }
        __syncthreads();
#pragma unroll
        for (int k = 0; k < 32; k++) {
            float4 a4 = *(const float4*)&As[k][ty << 2];
            float4 w0 = *(const float4*)&Ws[k][tx << 3];
            float4 w1 = *(const float4*)&Ws[k][(tx << 3) + 4];
            float a[4] = {a4.x, a4.y, a4.z, a4.w};
            float w[8] = {w0.x, w0.y, w0.z, w0.w, w1.x, w1.y, w1.z, w1.w};
#pragma unroll
            for (int r = 0; r < 4; r++)
#pragma unroll
                for (int c = 0; c < 8; c++) acc[r][c] += a[r] * w[c];
        }
        __syncthreads();
    }

    const float* bsrc   = (by == 0) ? wq_b : wv1_b;
    const int    colOff = (by == 0) ? 0 : 64;
    float b[8];
#pragma unroll
    for (int c = 0; c < 8; c++) b[c] = bsrc[(tx << 3) + c];
#pragma unroll
    for (int r = 0; r < 4; r++) {
        int row = row0 + (ty << 2) + r;
        float* dst = g_Y + row * 128 + colOff + (tx << 3);
        float4 v0 = make_float4(acc[r][0] + b[0], acc[r][1] + b[1],
                                acc[r][2] + b[2], acc[r][3] + b[3]);
        float4 v1 = make_float4(acc[r][4] + b[4], acc[r][5] + b[5],
                                acc[r][6] + b[6], acc[r][7] + b[7]);
        *(float4*)dst       = v0;
        *(float4*)(dst + 4) = v1;
    }
}

// ---------------------------------------------------------------------------
// Kernel 2: per-group attention + value path. One CTA = 8 groups = 64 rows.
//   qk = query @ wk_w ; scores = scale*(qk.act + query.wk_b), diag-masked
//   softmax ; s = sum_j attn * relu(Hh[j] + Wv1a@act[n,j]) ; out = s@wv2^T+b2
// ---------------------------------------------------------------------------
#define OFF_ACT   0                       // actT[8][32][64]         16384
#define OFF_Q     16384                   // query[64][PAD]           4352
#define OFF_HH    (OFF_Q + 64 * PAD)      // Hh[64][PAD]              4352
#define OFF_S     (OFF_HH + 64 * PAD)     // s[64][PAD]               4352
#define OFF_QK    (OFF_S + 64 * PAD)      // qk[64][32]               2048
#define OFF_ATTN  (OFF_QK + 2048)         // attn[64][8]               512
#define OFF_WKT   (OFF_ATTN + 512)        // wkT[32][64]              2048
#define OFF_WKB   (OFF_WKT + 2048)        // wk_b[64]                   64
#define OFF_WV1A  (OFF_WKB + 64)          // wv1a[32][64]             2048
#define OFF_WV2   (OFF_WV1A + 2048)       // wv2[32][64]              2048
#define SMEM_FLOATS (OFF_WV2 + 2048)      // 38208 floats = 152832 B

__global__ __launch_bounds__(512) void k2_attn(
    const float* __restrict__ actions,
    const float* __restrict__ wk_w, const float* __restrict__ wk_b,
    const float* __restrict__ wv1_w,
    const float* __restrict__ wv2_w, const float* __restrict__ wv2_b,
    float* __restrict__ out)
{
    extern __shared__ float sm[];
    float* actT  = sm + OFF_ACT;   // [g][k][pair]  pair = i*8+j
    float* Qs    = sm + OFF_Q;
    float* HHs   = sm + OFF_HH;
    float* Ss    = sm + OFF_S;
    float* QKs   = sm + OFF_QK;
    float* ATTNs = sm + OFF_ATTN;
    float* WKT   = sm + OFF_WKT;   // [m][d]
    float* WKB   = sm + OFF_WKB;
    float* WV1A  = sm + OFF_WV1A;  // [k][c]
    float* WV2   = sm + OFF_WV2;   // [p][c]

    const int tid = threadIdx.x;
    const int G0  = blockIdx.x * 64;      // first row of this CTA

    // ---- P1: stage everything ----
#pragma unroll
    for (int i = 0; i < 4; i++) {         // Y rows (query|Hh): 2048 float4
        int idx = tid + i * 512;
        int row = idx >> 5;
        int c4  = (idx & 31) << 2;
        float4 v = *(const float4*)(g_Y + (G0 + row) * 128 + c4);
        float* dst = (c4 < 64) ? (Qs + row * PAD + c4) : (HHs + row * PAD + (c4 - 64));
        *(float4*)dst = v;
    }
#pragma unroll
    for (int i = 0; i < 8; i++) {         // actions: 4096 float4, transpose per group
        int idx  = tid + i * 512;
        int pair = idx >> 3;              // 0..511
        int m4   = (idx & 7) << 2;
        float4 v = *(const float4*)(actions + G0 * 256 + pair * 32 + m4);
        int g   = pair >> 6;
        int p64 = pair & 63;
        float* base = actT + g * 2048 + p64;
        base[(m4 + 0) * 64] = v.x;
        base[(m4 + 1) * 64] = v.y;
        base[(m4 + 2) * 64] = v.z;
        base[(m4 + 3) * 64] = v.w;
    }
#pragma unroll
    for (int i = 0; i < 4; i++) {         // wk transposed: [d][m] -> [m][d]
        int idx = tid + i * 512;
        int d = idx >> 5, m = idx & 31;
        WKT[m * 64 + d] = wk_w[idx];
    }
    if (tid < 64) WKB[tid] = wk_b[tid];
#pragma unroll
    for (int i = 0; i < 4; i++) {         // wv1 action part: [c][256+k] -> [k][c]
        int idx = tid + i * 512;
        int c = idx >> 5, k = idx & 31;
        WV1A[k * 64 + c] = wv1_w[c * 288 + 256 + k];
    }
#pragma unroll
    for (int i = 0; i < 4; i++) {         // wv2 flat copy [p][c]
        int idx = tid + i * 512;
        WV2[idx] = wv2_w[idx];
    }
    __syncthreads();

    // ---- P2: qk[64][32] = query @ wk_w ----
    {
        int m  = tid & 31;
        int rb = tid >> 5;                // 0..15 -> rows rb*4..rb*4+3
        float acc[4] = {0.f, 0.f, 0.f, 0.f};
#pragma unroll
        for (int d4 = 0; d4 < 16; d4++) {
            float4 w4 = *(const float4*)&WKT[m * 64 + (d4 << 2)];
#pragma unroll
            for (int rr = 0; rr < 4; rr++) {
                float4 a4 = *(const float4*)&Qs[(rb * 4 + rr) * PAD + (d4 << 2)];
                acc[rr] += a4.x * w4.x + a4.y * w4.y + a4.z * w4.z + a4.w * w4.w;
            }
        }
#pragma unroll
        for (int rr = 0; rr < 4; rr++)
            QKs[(rb * 4 + rr) * 32 + m] = acc[rr];
    }
    __syncthreads();

    // ---- P3: masked scores + softmax -> attn ----
    if (tid < 64) {
        int r = tid, g = r >> 3, irow = r & 7;
        float qkb = 0.f;                  // query . wk_b (key bias term)
#pragma unroll
        for (int d = 0; d < 64; d++) qkb += Qs[r * PAD + d] * WKB[d];
        float sc[8] = {0, 0, 0, 0, 0, 0, 0, 0};
#pragma unroll
        for (int m = 0; m < 32; m++) {
            float qv = QKs[r * 32 + m];
            const float* ap = actT + g * 2048 + m * 64 + irow * 8;
#pragma unroll
            for (int j = 0; j < 8; j++) sc[j] += qv * ap[j];
        }
        float mx = -1e30f;
#pragma unroll
        for (int j = 0; j < 8; j++) {
            sc[j] = (j == irow) ? -1e9f : (sc[j] + qkb) * 0.125f;  // scale = 1/sqrt(64)
            mx = fmaxf(mx, sc[j]);
        }
        float sum = 0.f;
#pragma unroll
        for (int j = 0; j < 8; j++) { sc[j] = expf(sc[j] - mx); sum += sc[j]; }
        float inv = 1.f / sum;
#pragma unroll
        for (int j = 0; j < 8; j++) ATTNs[r * 8 + j] = sc[j] * inv;
    }
    __syncthreads();

    // ---- P4: Ha GEMM + relu + attn-weighted sum -> s[64][64] ----
    {
        int g  = tid >> 6;
        int i  = (tid >> 3) & 7;
        int co = tid & 7;
        int c0 = co << 3;
        float sacc[8] = {0, 0, 0, 0, 0, 0, 0, 0};
#pragma unroll
        for (int jh = 0; jh < 8; jh += 4) {
            float acc[4][8];
#pragma unroll
            for (int jj = 0; jj < 4; jj++)
#pragma unroll
                for (int c = 0; c < 8; c++) acc[jj][c] = 0.f;
            const float* aBase = actT + g * 2048 + i * 8 + jh;
#pragma unroll
            for (int k = 0; k < 32; k++) {
                float a0 = aBase[k * 64 + 0];
                float a1 = aBase[k * 64 + 1];
                float a2 = aBase[k * 64 + 2];
                float a3 = aBase[k * 64 + 3];
                float4 w0 = *(const float4*)&WV1A[k * 64 + c0];
                float4 w1 = *(const float4*)&WV1A[k * 64 + c0 + 4];
                float w[8] = {w0.x, w0.y, w0.z, w0.w, w1.x, w1.y, w1.z, w1.w};
#pragma unroll
                for (int c = 0; c < 8; c++) {
                    acc[0][c] += a0 * w[c];
                    acc[1][c] += a1 * w[c];
                    acc[2][c] += a2 * w[c];
                    acc[3][c] += a3 * w[c];
                }
            }
#pragma unroll
            for (int jj = 0; jj < 4; jj++) {
                int j = jh + jj;
                float at = ATTNs[(g * 8 + i) * 8 + j];
                const float* hh = HHs + (g * 8 + j) * PAD + c0;
#pragma unroll
                for (int c = 0; c < 8; c++) {
                    float v = acc[jj][c] + hh[c];   // Hh already has wv1_b folded in
                    v = fmaxf(v, 0.f);
                    sacc[c] += at * v;
                }
            }
        }
        float* sp = Ss + (g * 8 + i) * PAD + c0;
        *(float4*)sp       = make_float4(sacc[0], sacc[1], sacc[2], sacc[3]);
        *(float4*)(sp + 4) = make_float4(sacc[4], sacc[5], sacc[6], sacc[7]);
    }
    __syncthreads();

    // ---- P5: out[64][32] = s @ wv2^T + wv2_b ----
    {
        int p  = tid & 31;
        int rb = tid >> 5;                // 0..15
        float acc[4] = {0, 0, 0, 0};
#pragma unroll
        for (int c4 = 0; c4 < 16; c4++) {
            float4 w4 = *(const float4*)&WV2[p * 64 + (c4 << 2)];
#pragma unroll
            for (int rr = 0; rr < 4; rr++) {
                float4 s4 = *(const float4*)&Ss[(rb * 4 + rr) * PAD + (c4 << 2)];
                acc[rr] += s4.x * w4.x + s4.y * w4.y + s4.z * w4.z + s4.w * w4.w;
            }
        }
        float bb = wv2_b[p];
#pragma unroll
        for (int rr = 0; rr < 4; rr++)
            out[(G0 + rb * 4 + rr) * 32 + p] = acc[rr] + bb;
    }
}

// ---------------------------------------------------------------------------
extern "C" void kernel_launch(void* const* d_in, const int* in_sizes, int n_in,
                              void* d_out, int out_size) {
    const float* o       = (const float*)d_in[0];
    const float* o_next  = (const float*)d_in[1];
    const float* h       = (const float*)d_in[2];
    const float* actions = (const float*)d_in[3];
    const float* wq_w    = (const float*)d_in[4];
    const float* wq_b    = (const float*)d_in[5];
    const float* wk_w    = (const float*)d_in[6];
    const float* wk_b    = (const float*)d_in[7];
    const float* wv1_w   = (const float*)d_in[8];
    const float* wv1_b   = (const float*)d_in[9];
    const float* wv2_w   = (const float*)d_in[10];
    const float* wv2_b   = (const float*)d_in[11];
    float* out = (float*)d_out;

    cudaFuncSetAttribute(k2_attn, cudaFuncAttributeMaxDynamicSharedMemorySize,
                         SMEM_FLOATS * 4);

    dim3 g1(N_ROWS / 64, 2);
    k1_gemm<<<g1, 128>>>(o, o_next, h, wq_w, wq_b, wv1_w, wv1_b);
    k2_attn<<<NGROUPS / 8, 512, SMEM_FLOATS * 4>>>(actions, wk_w, wk_b, wv1_w,
                                                   wv2_w, wv2_b, out);
}

// round 14
// speedup vs baseline: 1.0024x; 1.0024x over previous
#include <cuda_runtime.h>

// Problem constants
#define N_ROWS  65536      // B*A rows
#define NGROUPS 8192       // batches (groups of 8 agents)
#define PAD     68         // padded row width for smem (breaks bank conflicts, keeps 16B align)

// Scratch: Y[n][0:64] = query(n), Y[n][64:128] = Hh(n) (+wv1_b folded in)
__device__ float g_Y[N_ROWS * 128];

// ---------------------------------------------------------------------------
// Kernel 1: two fused SGEMMs (M=65536, N=64, K=256)
//   by==0: query = [o|o_next] @ wq_w^T + wq_b
//   by==1: Hh    = h @ wv1_w[:, :256]^T + wv1_b
// Tile: 64 rows x 64 cols, BK=32, 128 threads, 4x8 register tile per thread.
// ---------------------------------------------------------------------------
__global__ __launch_bounds__(128) void k1_gemm(
    const float* __restrict__ o, const float* __restrict__ o_next,
    const float* __restrict__ h,
    const float* __restrict__ wq_w, const float* __restrict__ wq_b,
    const float* __restrict__ wv1_w, const float* __restrict__ wv1_b)
{
    __shared__ float As[32][PAD];   // k-major: As[k][row]
    __shared__ float Ws[32][PAD];   // k-major: Ws[k][col]
    const int by   = blockIdx.y;
    const int row0 = blockIdx.x * 64;
    const int tid  = threadIdx.x;
    const int tx   = tid & 7;       // col group (8 cols)
    const int ty   = tid >> 3;      // row group (4 rows)
    const float* Wsrc   = (by == 0) ? wq_w : wv1_w;
    const int    wstrid = (by == 0) ? 256  : 288;

    float acc[4][8];
#pragma unroll
    for (int r = 0; r < 4; r++)
#pragma unroll
        for (int c = 0; c < 8; c++) acc[r][c] = 0.f;

    for (int kt = 0; kt < 8; kt++) {
        const int k0 = kt * 32;
        // Load A tile (64 rows x 32 k), transposed into k-major smem
#pragma unroll
        for (int i = 0; i < 4; i++) {
            int flat = tid + i * 128;          // 0..511 float4 slots
            int r    = flat >> 3;              // 0..63
            int k4   = (flat & 7) << 2;        // 0..28
            int kg   = k0 + k4;
            float4 v;
            if (by == 0) {
                if (kg < 128) v = *(const float4*)(o      + (row0 + r) * 128 + kg);
                else          v = *(const float4*)(o_next + (row0 + r) * 128 + (kg - 128));
            } else {
                v = *(const float4*)(h + (row0 + r) * 256 + kg);
            }
            As[k4 + 0][r] = v.x; As[k4 + 1][r] = v.y;
            As[k4 + 2][r] = v.z; As[k4 + 3][r] = v.w;
        }
        // Load W tile (64 cols x 32 k), transposed into k-major smem
#pragma unroll
        for (int i = 0; i < 4; i++) {
            int flat = tid + i * 128;
            int c    = flat >> 3;
            int k4   = (flat & 7) << 2;
            float4 v = *(const float4*)(Wsrc + c * wstrid + k0 + k4);
            Ws[k4 + 0][c] = v.x; Ws[k4 + 1][c] = v.y;
            Ws[k4 + 2][c] = v.z; Ws[k4 + 3][c] = v.w;
        }
        __syncthreads();
#pragma unroll
        for (int k = 0; k < 32; k++) {
            float4 a4 = *(const float4*)&As[k][ty << 2];
            float4 w0 = *(const float4*)&Ws[k][tx << 3];
            float4 w1 = *(const float4*)&Ws[k][(tx << 3) + 4];
            float a[4] = {a4.x, a4.y, a4.z, a4.w};
            float w[8] = {w0.x, w0.y, w0.z, w0.w, w1.x, w1.y, w1.z, w1.w};
#pragma unroll
            for (int r = 0; r < 4; r++)
#pragma unroll
                for (int c = 0; c < 8; c++) acc[r][c] += a[r] * w[c];
        }
        __syncthreads();
    }

    const float* bsrc   = (by == 0) ? wq_b : wv1_b;
    const int    colOff = (by == 0) ? 0 : 64;
    float b[8];
#pragma unroll
    for (int c = 0; c < 8; c++) b[c] = bsrc[(tx << 3) + c];
#pragma unroll
    for (int r = 0; r < 4; r++) {
        int row = row0 + (ty << 2) + r;
        float* dst = g_Y + row * 128 + colOff + (tx << 3);
        float4 v0 = make_float4(acc[r][0] + b[0], acc[r][1] + b[1],
                                acc[r][2] + b[2], acc[r][3] + b[3]);
        float4 v1 = make_float4(acc[r][4] + b[4], acc[r][5] + b[5],
                                acc[r][6] + b[6], acc[r][7] + b[7]);
        *(float4*)dst       = v0;
        *(float4*)(dst + 4) = v1;
    }
}

// ---------------------------------------------------------------------------
// Kernel 2: per-group attention + value path. One CTA = 8 groups = 64 rows.
//   qk = query @ wk_w ; scores = scale*(qk.act + query.wk_b), diag-masked
//   softmax ; s = sum_j attn * relu(Hh[j] + Wv1a@act[n,j]) ; out = s@wv2^T+b2
// ---------------------------------------------------------------------------
#define OFF_ACT   0                       // actT[8][32][64]         16384
#define OFF_Q     16384                   // query[64][PAD]           4352
#define OFF_HH    (OFF_Q + 64 * PAD)      // Hh[64][PAD]              4352
#define OFF_S     (OFF_HH + 64 * PAD)     // s[64][PAD]               4352
#define OFF_QK    (OFF_S + 64 * PAD)      // qk[64][32]               2048
#define OFF_ATTN  (OFF_QK + 2048)         // attn[64][8]               512
#define OFF_WKT   (OFF_ATTN + 512)        // wkT[32][64]              2048
#define OFF_WKB   (OFF_WKT + 2048)        // wk_b[64]                   64
#define OFF_WV1A  (OFF_WKB + 64)          // wv1a[32][64]             2048
#define OFF_WV2   (OFF_WV1A + 2048)       // wv2[32][64]              2048
#define SMEM_FLOATS (OFF_WV2 + 2048)      // 38208 floats = 152832 B

__global__ __launch_bounds__(512) void k2_attn(
    const float* __restrict__ actions,
    const float* __restrict__ wk_w, const float* __restrict__ wk_b,
    const float* __restrict__ wv1_w,
    const float* __restrict__ wv2_w, const float* __restrict__ wv2_b,
    float* __restrict__ out)
{
    extern __shared__ float sm[];
    float* actT  = sm + OFF_ACT;   // [g][k][pair]  pair = i*8+j
    float* Qs    = sm + OFF_Q;
    float* HHs   = sm + OFF_HH;
    float* Ss    = sm + OFF_S;
    float* QKs   = sm + OFF_QK;
    float* ATTNs = sm + OFF_ATTN;
    float* WKT   = sm + OFF_WKT;   // [m][d]
    float* WKB   = sm + OFF_WKB;
    float* WV1A  = sm + OFF_WV1A;  // [k][c]
    float* WV2   = sm + OFF_WV2;   // [p][c]

    const int tid = threadIdx.x;
    const int G0  = blockIdx.x * 64;      // first row of this CTA

    // ---- P1: stage everything ----
#pragma unroll
    for (int i = 0; i < 4; i++) {         // Y rows (query|Hh): 2048 float4
        int idx = tid + i * 512;
        int row = idx >> 5;
        int c4  = (idx & 31) << 2;
        float4 v = *(const float4*)(g_Y + (G0 + row) * 128 + c4);
        float* dst = (c4 < 64) ? (Qs + row * PAD + c4) : (HHs + row * PAD + (c4 - 64));
        *(float4*)dst = v;
    }
#pragma unroll
    for (int i = 0; i < 8; i++) {         // actions: 4096 float4, transpose per group
        int idx  = tid + i * 512;
        int pair = idx >> 3;              // 0..511
        int m4   = (idx & 7) << 2;
        float4 v = *(const float4*)(actions + G0 * 256 + pair * 32 + m4);
        int g   = pair >> 6;
        int p64 = pair & 63;
        float* base = actT + g * 2048 + p64;
        base[(m4 + 0) * 64] = v.x;
        base[(m4 + 1) * 64] = v.y;
        base[(m4 + 2) * 64] = v.z;
        base[(m4 + 3) * 64] = v.w;
    }
#pragma unroll
    for (int i = 0; i < 4; i++) {         // wk transposed: [d][m] -> [m][d]
        int idx = tid + i * 512;
        int d = idx >> 5, m = idx & 31;
        WKT[m * 64 + d] = wk_w[idx];
    }
    if (tid < 64) WKB[tid] = wk_b[tid];
#pragma unroll
    for (int i = 0; i < 4; i++) {         // wv1 action part: [c][256+k] -> [k][c]
        int idx = tid + i * 512;
        int c = idx >> 5, k = idx & 31;
        WV1A[k * 64 + c] = wv1_w[c * 288 + 256 + k];
    }
#pragma unroll
    for (int i = 0; i < 4; i++) {         // wv2 flat copy [p][c]
        int idx = tid + i * 512;
        WV2[idx] = wv2_w[idx];
    }
    __syncthreads();

    // ---- P2: qk[64][32] = query @ wk_w ----
    {
        int m  = tid & 31;
        int rb = tid >> 5;                // 0..15 -> rows rb*4..rb*4+3
        float acc[4] = {0.f, 0.f, 0.f, 0.f};
#pragma unroll
        for (int d4 = 0; d4 < 16; d4++) {
            float4 w4 = *(const float4*)&WKT[m * 64 + (d4 << 2)];
#pragma unroll
            for (int rr = 0; rr < 4; rr++) {
                float4 a4 = *(const float4*)&Qs[(rb * 4 + rr) * PAD + (d4 << 2)];
                acc[rr] += a4.x * w4.x + a4.y * w4.y + a4.z * w4.z + a4.w * w4.w;
            }
        }
#pragma unroll
        for (int rr = 0; rr < 4; rr++)
            QKs[(rb * 4 + rr) * 32 + m] = acc[rr];
    }
    __syncthreads();

    // ---- P3: masked scores + softmax -> attn ----
    if (tid < 64) {
        int r = tid, g = r >> 3, irow = r & 7;
        float qkb = 0.f;                  // query . wk_b (key bias term)
#pragma unroll
        for (int d = 0; d < 64; d++) qkb += Qs[r * PAD + d] * WKB[d];
        float sc[8] = {0, 0, 0, 0, 0, 0, 0, 0};
#pragma unroll
        for (int m = 0; m < 32; m++) {
            float qv = QKs[r * 32 + m];
            const float* ap = actT + g * 2048 + m * 64 + irow * 8;
#pragma unroll
            for (int j = 0; j < 8; j++) sc[j] += qv * ap[j];
        }
        float mx = -1e30f;
#pragma unroll
        for (int j = 0; j < 8; j++) {
            sc[j] = (j == irow) ? -1e9f : (sc[j] + qkb) * 0.125f;  // scale = 1/sqrt(64)
            mx = fmaxf(mx, sc[j]);
        }
        float sum = 0.f;
#pragma unroll
        for (int j = 0; j < 8; j++) { sc[j] = expf(sc[j] - mx); sum += sc[j]; }
        float inv = 1.f / sum;
#pragma unroll
        for (int j = 0; j < 8; j++) ATTNs[r * 8 + j] = sc[j] * inv;
    }
    __syncthreads();

    // ---- P4: Ha GEMM + relu + attn-weighted sum -> s[64][64] ----
    {
        int g  = tid >> 6;
        int i  = (tid >> 3) & 7;
        int co = tid & 7;
        int c0 = co << 3;
        float sacc[8] = {0, 0, 0, 0, 0, 0, 0, 0};
#pragma unroll
        for (int jh = 0; jh < 8; jh += 4) {
            float acc[4][8];
#pragma unroll
            for (int jj = 0; jj < 4; jj++)
#pragma unroll
                for (int c = 0; c < 8; c++) acc[jj][c] = 0.f;
            const float* aBase = actT + g * 2048 + i * 8 + jh;
#pragma unroll
            for (int k = 0; k < 32; k++) {
                float a0 = aBase[k * 64 + 0];
                float a1 = aBase[k * 64 + 1];
                float a2 = aBase[k * 64 + 2];
                float a3 = aBase[k * 64 + 3];
                float4 w0 = *(const float4*)&WV1A[k * 64 + c0];
                float4 w1 = *(const float4*)&WV1A[k * 64 + c0 + 4];
                float w[8] = {w0.x, w0.y, w0.z, w0.w, w1.x, w1.y, w1.z, w1.w};
#pragma unroll
                for (int c = 0; c < 8; c++) {
                    acc[0][c] += a0 * w[c];
                    acc[1][c] += a1 * w[c];
                    acc[2][c] += a2 * w[c];
                    acc[3][c] += a3 * w[c];
                }
            }
#pragma unroll
            for (int jj = 0; jj < 4; jj++) {
                int j = jh + jj;
                float at = ATTNs[(g * 8 + i) * 8 + j];
                const float* hh = HHs + (g * 8 + j) * PAD + c0;
#pragma unroll
                for (int c = 0; c < 8; c++) {
                    float v = acc[jj][c] + hh[c];   // Hh already has wv1_b folded in
                    v = fmaxf(v, 0.f);
                    sacc[c] += at * v;
                }
            }
        }
        float* sp = Ss + (g * 8 + i) * PAD + c0;
        *(float4*)sp       = make_float4(sacc[0], sacc[1], sacc[2], sacc[3]);
        *(float4*)(sp + 4) = make_float4(sacc[4], sacc[5], sacc[6], sacc[7]);
    }
    __syncthreads();

    // ---- P5: out[64][32] = s @ wv2^T + wv2_b ----
    {
        int p  = tid & 31;
        int rb = tid >> 5;                // 0..15
        float acc[4] = {0, 0, 0, 0};
#pragma unroll
        for (int c4 = 0; c4 < 16; c4++) {
            float4 w4 = *(const float4*)&WV2[p * 64 + (c4 << 2)];
#pragma unroll
            for (int rr = 0; rr < 4; rr++) {
                float4 s4 = *(const float4*)&Ss[(rb * 4 + rr) * PAD + (c4 << 2)];
                acc[rr] += s4.x * w4.x + s4.y * w4.y + s4.z * w4.z + s4.w * w4.w;
            }
        }
        float bb = wv2_b[p];
#pragma unroll
        for (int rr = 0; rr < 4; rr++)
            out[(G0 + rb * 4 + rr) * 32 + p] = acc[rr] + bb;
    }
}

// ---------------------------------------------------------------------------
extern "C" void kernel_launch(void* const* d_in, const int* in_sizes, int n_in,
                              void* d_out, int out_size) {
    const float* o       = (const float*)d_in[0];
    const float* o_next  = (const float*)d_in[1];
    const float* h       = (const float*)d_in[2];
    const float* actions = (const float*)d_in[3];
    const float* wq_w    = (const float*)d_in[4];
    const float* wq_b    = (const float*)d_in[5];
    const float* wk_w    = (const float*)d_in[6];
    const float* wk_b    = (const float*)d_in[7];
    const float* wv1_w   = (const float*)d_in[8];
    const float* wv1_b   = (const float*)d_in[9];
    const float* wv2_w   = (const float*)d_in[10];
    const float* wv2_b   = (const float*)d_in[11];
    float* out = (float*)d_out;

    cudaFuncSetAttribute(k2_attn, cudaFuncAttributeMaxDynamicSharedMemorySize,
                         SMEM_FLOATS * 4);

    dim3 g1(N_ROWS / 64, 2);
    k1_gemm<<<g1, 128>>>(o, o_next, h, wq_w, wq_b, wv1_w, wv1_b);
    k2_attn<<<NGROUPS / 8, 512, SMEM_FLOATS * 4>>>(actions, wk_w, wk_b, wv1_w,
                                                   wv2_w, wv2_b, out);
}

// round 15
// speedup vs baseline: 1.0041x; 1.0017x over previous
#include <cuda_runtime.h>

// Problem constants
#define N_ROWS  65536      // B*A rows
#define NGROUPS 8192       // batches (groups of 8 agents)
#define PAD     68         // padded row width for smem (breaks bank conflicts, keeps 16B align)

// Scratch: Y[n][0:64] = query(n), Y[n][64:128] = Hh(n) (+wv1_b folded in)
__device__ float g_Y[N_ROWS * 128];

// ---------------------------------------------------------------------------
// Kernel 1: two fused SGEMMs (M=65536, N=64, K=256)
//   by==0: query = [o|o_next] @ wq_w^T + wq_b
//   by==1: Hh    = h @ wv1_w[:, :256]^T + wv1_b
// Tile: 64 rows x 64 cols, BK=32, 128 threads, 4x8 register tile per thread.
// ---------------------------------------------------------------------------
__global__ __launch_bounds__(128) void k1_gemm(
    const float* __restrict__ o, const float* __restrict__ o_next,
    const float* __restrict__ h,
    const float* __restrict__ wq_w, const float* __restrict__ wq_b,
    const float* __restrict__ wv1_w, const float* __restrict__ wv1_b)
{
    __shared__ float As[32][PAD];   // k-major: As[k][row]
    __shared__ float Ws[32][PAD];   // k-major: Ws[k][col]
    const int by   = blockIdx.y;
    const int row0 = blockIdx.x * 64;
    const int tid  = threadIdx.x;
    const int tx   = tid & 7;       // col group (8 cols)
    const int ty   = tid >> 3;      // row group (4 rows)
    const float* Wsrc   = (by == 0) ? wq_w : wv1_w;
    const int    wstrid = (by == 0) ? 256  : 288;

    float acc[4][8];
#pragma unroll
    for (int r = 0; r < 4; r++)
#pragma unroll
        for (int c = 0; c < 8; c++) acc[r][c] = 0.f;

    for (int kt = 0; kt < 8; kt++) {
        const int k0 = kt * 32;
        // Load A tile (64 rows x 32 k), transposed into k-major smem
#pragma unroll
        for (int i = 0; i < 4; i++) {
            int flat = tid + i * 128;          // 0..511 float4 slots
            int r    = flat >> 3;              // 0..63
            int k4   = (flat & 7) << 2;        // 0..28
            int kg   = k0 + k4;
            float4 v;
            if (by == 0) {
                if (kg < 128) v = *(const float4*)(o      + (row0 + r) * 128 + kg);
                else          v = *(const float4*)(o_next + (row0 + r) * 128 + (kg - 128));
            } else {
                v = *(const float4*)(h + (row0 + r) * 256 + kg);
            }
            As[k4 + 0][r] = v.x; As[k4 + 1][r] = v.y;
            As[k4 + 2][r] = v.z; As[k4 + 3][r] = v.w;
        }
        // Load W tile (64 cols x 32 k), transposed into k-major smem
#pragma unroll
        for (int i = 0; i < 4; i++) {
            int flat = tid + i * 128;
            int c    = flat >> 3;
            int k4   = (flat & 7) << 2;
            float4 v = *(const float4*)(Wsrc + c * wstrid + k0 + k4);
            Ws[k4 + 0][c] = v.x; Ws[k4 + 1][c] = v.y;
            Ws[k4 + 2][c] = v.z; Ws[k4 + 3][c] = v.w;
        }
        __syncthreads();
#pragma unroll
        for (int k = 0; k < 32; k++) {
            float4 a4 = *(const float4*)&As[k][ty << 2];
            float4 w0 = *(const float4*)&Ws[k][tx << 3];
            float4 w1 = *(const float4*)&Ws[k][(tx << 3) + 4];
            float a[4] = {a4.x, a4.y, a4.z, a4.w};
            float w[8] = {w0.x, w0.y, w0.z, w0.w, w1.x, w1.y, w1.z, w1.w};
#pragma unroll
            for (int r = 0; r < 4; r++)
#pragma unroll
                for (int c = 0; c < 8; c++) acc[r][c] += a[r] * w[c];
        }
        __syncthreads();
    }

    const float* bsrc   = (by == 0) ? wq_b : wv1_b;
    const int    colOff = (by == 0) ? 0 : 64;
    float b[8];
#pragma unroll
    for (int c = 0; c < 8; c++) b[c] = bsrc[(tx << 3) + c];
#pragma unroll
    for (int r = 0; r < 4; r++) {
        int row = row0 + (ty << 2) + r;
        float* dst = g_Y + row * 128 + colOff + (tx << 3);
        float4 v0 = make_float4(acc[r][0] + b[0], acc[r][1] + b[1],
                                acc[r][2] + b[2], acc[r][3] + b[3]);
        float4 v1 = make_float4(acc[r][4] + b[4], acc[r][5] + b[5],
                                acc[r][6] + b[6], acc[r][7] + b[7]);
        *(float4*)dst       = v0;
        *(float4*)(dst + 4) = v1;
    }
}

// ---------------------------------------------------------------------------
// Kernel 2: per-group attention + value path. One CTA = 8 groups = 64 rows.
//   qk = query @ wk_w ; scores = scale*(qk.act + query.wk_b), diag-masked
//   softmax ; s = sum_j attn * relu(Hh[j] + Wv1a@act[n,j]) ; out = s@wv2^T+b2
// ---------------------------------------------------------------------------
#define OFF_ACT   0                       // actT[8][32][64]         16384
#define OFF_Q     16384                   // query[64][PAD]           4352
#define OFF_HH    (OFF_Q + 64 * PAD)      // Hh[64][PAD]              4352
#define OFF_S     (OFF_HH + 64 * PAD)     // s[64][PAD]               4352
#define OFF_QK    (OFF_S + 64 * PAD)      // qk[64][32]               2048
#define OFF_ATTN  (OFF_QK + 2048)         // attn[64][8]               512
#define OFF_WKT   (OFF_ATTN + 512)        // wkT[32][64]              2048
#define OFF_WKB   (OFF_WKT + 2048)        // wk_b[64]                   64
#define OFF_WV1A  (OFF_WKB + 64)          // wv1a[32][64]             2048
#define OFF_WV2   (OFF_WV1A + 2048)       // wv2[32][64]              2048
#define SMEM_FLOATS (OFF_WV2 + 2048)      // 38208 floats = 152832 B

__global__ __launch_bounds__(512) void k2_attn(
    const float* __restrict__ actions,
    const float* __restrict__ wk_w, const float* __restrict__ wk_b,
    const float* __restrict__ wv1_w,
    const float* __restrict__ wv2_w, const float* __restrict__ wv2_b,
    float* __restrict__ out)
{
    extern __shared__ float sm[];
    float* actT  = sm + OFF_ACT;   // [g][k][pair]  pair = i*8+j
    float* Qs    = sm + OFF_Q;
    float* HHs   = sm + OFF_HH;
    float* Ss    = sm + OFF_S;
    float* QKs   = sm + OFF_QK;
    float* ATTNs = sm + OFF_ATTN;
    float* WKT   = sm + OFF_WKT;   // [m][d]
    float* WKB   = sm + OFF_WKB;
    float* WV1A  = sm + OFF_WV1A;  // [k][c]
    float* WV2   = sm + OFF_WV2;   // [p][c]

    const int tid = threadIdx.x;
    const int G0  = blockIdx.x * 64;      // first row of this CTA

    // ---- P1: stage everything ----
#pragma unroll
    for (int i = 0; i < 4; i++) {         // Y rows (query|Hh): 2048 float4
        int idx = tid + i * 512;
        int row = idx >> 5;
        int c4  = (idx & 31) << 2;
        float4 v = *(const float4*)(g_Y + (G0 + row) * 128 + c4);
        float* dst = (c4 < 64) ? (Qs + row * PAD + c4) : (HHs + row * PAD + (c4 - 64));
        *(float4*)dst = v;
    }
#pragma unroll
    for (int i = 0; i < 8; i++) {         // actions: 4096 float4, transpose per group
        int idx  = tid + i * 512;
        int pair = idx >> 3;              // 0..511
        int m4   = (idx & 7) << 2;
        float4 v = *(const float4*)(actions + G0 * 256 + pair * 32 + m4);
        int g   = pair >> 6;
        int p64 = pair & 63;
        float* base = actT + g * 2048 + p64;
        base[(m4 + 0) * 64] = v.x;
        base[(m4 + 1) * 64] = v.y;
        base[(m4 + 2) * 64] = v.z;
        base[(m4 + 3) * 64] = v.w;
    }
#pragma unroll
    for (int i = 0; i < 4; i++) {         // wk transposed: [d][m] -> [m][d]
        int idx = tid + i * 512;
        int d = idx >> 5, m = idx & 31;
        WKT[m * 64 + d] = wk_w[idx];
    }
    if (tid < 64) WKB[tid] = wk_b[tid];
#pragma unroll
    for (int i = 0; i < 4; i++) {         // wv1 action part: [c][256+k] -> [k][c]
        int idx = tid + i * 512;
        int c = idx >> 5, k = idx & 31;
        WV1A[k * 64 + c] = wv1_w[c * 288 + 256 + k];
    }
#pragma unroll
    for (int i = 0; i < 4; i++) {         // wv2 flat copy [p][c]
        int idx = tid + i * 512;
        WV2[idx] = wv2_w[idx];
    }
    __syncthreads();

    // ---- P2: qk[64][32] = query @ wk_w ----
    {
        int m  = tid & 31;
        int rb = tid >> 5;                // 0..15 -> rows rb*4..rb*4+3
        float acc[4] = {0.f, 0.f, 0.f, 0.f};
#pragma unroll
        for (int d4 = 0; d4 < 16; d4++) {
            float4 w4 = *(const float4*)&WKT[m * 64 + (d4 << 2)];
#pragma unroll
            for (int rr = 0; rr < 4; rr++) {
                float4 a4 = *(const float4*)&Qs[(rb * 4 + rr) * PAD + (d4 << 2)];
                acc[rr] += a4.x * w4.x + a4.y * w4.y + a4.z * w4.z + a4.w * w4.w;
            }
        }
#pragma unroll
        for (int rr = 0; rr < 4; rr++)
            QKs[(rb * 4 + rr) * 32 + m] = acc[rr];
    }
    __syncthreads();

    // ---- P3: masked scores + softmax -> attn ----
    if (tid < 64) {
        int r = tid, g = r >> 3, irow = r & 7;
        float qkb = 0.f;                  // query . wk_b (key bias term)
#pragma unroll
        for (int d = 0; d < 64; d++) qkb += Qs[r * PAD + d] * WKB[d];
        float sc[8] = {0, 0, 0, 0, 0, 0, 0, 0};
#pragma unroll
        for (int m = 0; m < 32; m++) {
            float qv = QKs[r * 32 + m];
            const float* ap = actT + g * 2048 + m * 64 + irow * 8;
#pragma unroll
            for (int j = 0; j < 8; j++) sc[j] += qv * ap[j];
        }
        float mx = -1e30f;
#pragma unroll
        for (int j = 0; j < 8; j++) {
            sc[j] = (j == irow) ? -1e9f : (sc[j] + qkb) * 0.125f;  // scale = 1/sqrt(64)
            mx = fmaxf(mx, sc[j]);
        }
        float sum = 0.f;
#pragma unroll
        for (int j = 0; j < 8; j++) { sc[j] = expf(sc[j] - mx); sum += sc[j]; }
        float inv = 1.f / sum;
#pragma unroll
        for (int j = 0; j < 8; j++) ATTNs[r * 8 + j] = sc[j] * inv;
    }
    __syncthreads();

    // ---- P4: Ha GEMM + relu + attn-weighted sum -> s[64][64] ----
    {
        int g  = tid >> 6;
        int i  = (tid >> 3) & 7;
        int co = tid & 7;
        int c0 = co << 3;
        float sacc[8] = {0, 0, 0, 0, 0, 0, 0, 0};
#pragma unroll
        for (int jh = 0; jh < 8; jh += 4) {
            float acc[4][8];
#pragma unroll
            for (int jj = 0; jj < 4; jj++)
#pragma unroll
                for (int c = 0; c < 8; c++) acc[jj][c] = 0.f;
            const float* aBase = actT + g * 2048 + i * 8 + jh;
#pragma unroll
            for (int k = 0; k < 32; k++) {
                float a0 = aBase[k * 64 + 0];
                float a1 = aBase[k * 64 + 1];
                float a2 = aBase[k * 64 + 2];
                float a3 = aBase[k * 64 + 3];
                float4 w0 = *(const float4*)&WV1A[k * 64 + c0];
                float4 w1 = *(const float4*)&WV1A[k * 64 + c0 + 4];
                float w[8] = {w0.x, w0.y, w0.z, w0.w, w1.x, w1.y, w1.z, w1.w};
#pragma unroll
                for (int c = 0; c < 8; c++) {
                    acc[0][c] += a0 * w[c];
                    acc[1][c] += a1 * w[c];
                    acc[2][c] += a2 * w[c];
                    acc[3][c] += a3 * w[c];
                }
            }
#pragma unroll
            for (int jj = 0; jj < 4; jj++) {
                int j = jh + jj;
                float at = ATTNs[(g * 8 + i) * 8 + j];
                const float* hh = HHs + (g * 8 + j) * PAD + c0;
#pragma unroll
                for (int c = 0; c < 8; c++) {
                    float v = acc[jj][c] + hh[c];   // Hh already has wv1_b folded in
                    v = fmaxf(v, 0.f);
                    sacc[c] += at * v;
                }
            }
        }
        float* sp = Ss + (g * 8 + i) * PAD + c0;
        *(float4*)sp       = make_float4(sacc[0], sacc[1], sacc[2], sacc[3]);
        *(float4*)(sp + 4) = make_float4(sacc[4], sacc[5], sacc[6], sacc[7]);
    }
    __syncthreads();

    // ---- P5: out[64][32] = s @ wv2^T + wv2_b ----
    {
        int p  = tid & 31;
        int rb = tid >> 5;                // 0..15
        float acc[4] = {0, 0, 0, 0};
#pragma unroll
        for (int c4 = 0; c4 < 16; c4++) {
            float4 w4 = *(const float4*)&WV2[p * 64 + (c4 << 2)];
#pragma unroll
            for (int rr = 0; rr < 4; rr++) {
                float4 s4 = *(const float4*)&Ss[(rb * 4 + rr) * PAD + (c4 << 2)];
                acc[rr] += s4.x * w4.x + s4.y * w4.y + s4.z * w4.z + s4.w * w4.w;
            }
        }
        float bb = wv2_b[p];
#pragma unroll
        for (int rr = 0; rr < 4; rr++)
            out[(G0 + rb * 4 + rr) * 32 + p] = acc[rr] + bb;
    }
}

// ---------------------------------------------------------------------------
extern "C" void kernel_launch(void* const* d_in, const int* in_sizes, int n_in,
                              void* d_out, int out_size) {
    const float* o       = (const float*)d_in[0];
    const float* o_next  = (const float*)d_in[1];
    const float* h       = (const float*)d_in[2];
    const float* actions = (const float*)d_in[3];
    const float* wq_w    = (const float*)d_in[4];
    const float* wq_b    = (const float*)d_in[5];
    const float* wk_w    = (const float*)d_in[6];
    const float* wk_b    = (const float*)d_in[7];
    const float* wv1_w   = (const float*)d_in[8];
    const float* wv1_b   = (const float*)d_in[9];
    const float* wv2_w   = (const float*)d_in[10];
    const float* wv2_b   = (const float*)d_in[11];
    float* out = (float*)d_out;

    cudaFuncSetAttribute(k2_attn, cudaFuncAttributeMaxDynamicSharedMemorySize,
                         SMEM_FLOATS * 4);

    dim3 g1(N_ROWS / 64, 2);
    k1_gemm<<<g1, 128>>>(o, o_next, h, wq_w, wq_b, wv1_w, wv1_b);
    k2_attn<<<NGROUPS / 8, 512, SMEM_FLOATS * 4>>>(actions, wk_w, wk_b, wv1_w,
                                                   wv2_w, wv2_b, out);
}